// round 12
// baseline (speedup 1.0000x reference)
#include <cuda_runtime.h>
#include <cuda_bf16.h>
#include <cstdint>

#define D 784
#define H 1024
#define BATCH 1024
#define THREADS 512
#define R 7                      // batch rows per CTA pair
#define NPAIRS 147               // 147*7 = 1029 >= 1024
#define NCTAS (2 * NPAIRS)       // 294: one CTA per (pair, D-half)
#define DHALF 392                // D / 2
#define CHUNK 98                 // 392 = 4 * 98 (even trip count)
#define NCHUNKS (DHALF / CHUNK)
#define SX_BYTES (D * 8 * 4)                 // sx8[D][8]
#define SP_BYTES (CHUNK * 16 * 8 * 4)        // sp[CHUNK][16][8]
#define SMEM_BYTES (SX_BYTES + SP_BYTES)     // 75264 (x2 CTAs = 147KB/SM)

// Scratch (no allocations allowed).
// g_VW[i*512 + t] = (V[i,2t], V[i,2t+1], W[2t,i], W[2t+1,i])
__device__ float4 g_VW[D * (H / 2)];
__device__ float  g_bias[D];          // bias[i] = b[i] + 0.5 * sum_h V[i,h]

// Two tanh evaluations in ONE MUFU op via f16x2.
__device__ __forceinline__ void tanh2(float a, float b, float& ta, float& tb) {
    uint32_t pk, tk;
    asm("cvt.rn.f16x2.f32 %0, %1, %2;" : "=r"(pk) : "f"(b), "f"(a)); // lo=a, hi=b
    asm("tanh.approx.f16x2 %0, %1;" : "=r"(tk) : "r"(pk));
    asm("{\n\t.reg .b16 l, h;\n\t"
        "mov.b32 {l, h}, %2;\n\t"
        "cvt.f32.f16 %0, l;\n\t"
        "cvt.f32.f16 %1, h;\n\t}"
        : "=f"(ta), "=f"(tb) : "r"(tk));
}

// ---------------------------------------------------------------------------
// Fused prep: blockIdx.y < 32 -> build interleaved g_VW tile (transpose W via
//                                smem tile, merge with V)
//             blockIdx.y == 32 -> bias[i] = b[i] + 0.5 * sum_h V[i,h]
// ---------------------------------------------------------------------------
__global__ void prep_kernel(const float* __restrict__ W,
                            const float* __restrict__ V,
                            const float* __restrict__ bvec) {
    if (blockIdx.y < 32) {
        __shared__ float tile[32][33];
        const int i0 = blockIdx.x * 32;
        const int h0 = blockIdx.y * 32;
        const int tx = threadIdx.x, ty = threadIdx.y;
        #pragma unroll
        for (int j = 0; j < 32; j += 8) {
            int ii = i0 + tx;
            if (ii < D) tile[ty + j][tx] = W[(h0 + ty + j) * D + ii];
        }
        __syncthreads();
        #pragma unroll
        for (int j = 0; j < 32; j += 8) {
            int i = i0 + ty + j;
            if (i < D && tx < 16) {
                int tcol = h0 / 2 + tx;
                float2 v2 = reinterpret_cast<const float2*>(V)[i * (H / 2) + tcol];
                g_VW[i * (H / 2) + tcol] =
                    make_float4(v2.x, v2.y, tile[2 * tx][i - i0], tile[2 * tx + 1][i - i0]);
            }
        }
    } else {
        int lane = threadIdx.x;
        int w    = threadIdx.y;
        #pragma unroll
        for (int k = 0; k < 4; k++) {
            int i = blockIdx.x * 32 + w * 4 + k;
            if (i >= D) continue;
            float s = 0.0f;
            #pragma unroll
            for (int j = 0; j < H / 32; j++) s += V[i * H + j * 32 + lane];
            #pragma unroll
            for (int o = 16; o > 0; o >>= 1)
                s += __shfl_xor_sync(0xffffffffu, s, o);
            if (lane == 0) g_bias[i] = bvec[i] + 0.5f * s;
        }
    }
}

// ---------------------------------------------------------------------------
// Main: CTA pairs split D. half=0 (bid<147) handles steps [0,392);
// half=1 (bid>=147) first replays [0,392) accumulate-only (bitwise-identical
// FMA sequence, no tanh/dot/reduce), then handles [392,784) fully.
// bid<->bid+148 co-residency puts one A + one B per SM -> 32 warps/SM.
// Full-step body is verbatim round 10 (software-pipelined prefetch,
// butterfly reduction, deferred chunk epilogue).
// ---------------------------------------------------------------------------
__global__ void __launch_bounds__(THREADS, 2)
nade_main(const float* __restrict__ pixels,
          const float* __restrict__ c,
          float* __restrict__ out) {
    extern __shared__ char smem_raw[];
    float* sx8 = reinterpret_cast<float*>(smem_raw);              // [D][8]
    float* sp  = reinterpret_cast<float*>(smem_raw + SX_BYTES);   // [CHUNK][16][8]

    const int half = (blockIdx.x >= NPAIRS) ? 1 : 0;
    const int pair = blockIdx.x - half * NPAIRS;
    const int b0   = pair * R;
    const int t    = threadIdx.x;
    const int lane = t & 31;
    const int wid  = t >> 5;

    for (int i = t; i < D; i += THREADS) {
        #pragma unroll
        for (int r = 0; r < R; r++) {
            int br = min(b0 + r, BATCH - 1);
            sx8[i * 8 + r] = 0.5f * pixels[br * D + i];
        }
        sx8[i * 8 + 7] = 0.0f;
    }

    float2 A[R];
    {
        float2 cc = reinterpret_cast<const float2*>(c)[t];
        cc.x *= 0.5f; cc.y *= 0.5f;
        #pragma unroll
        for (int r = 0; r < R; r++) A[r] = cc;
    }
    __syncthreads();

    const bool lo16 = (lane & 16) == 0;
    const bool lo8  = (lane & 8)  == 0;
    const bool lo4  = (lane & 4)  == 0;
    const int rowmap = ((lane >> 4) & 1) | (((lane >> 3) & 1) << 1)
                     | (((lane >> 2) & 1) << 2);
    const bool is_head = (lane & 3) == 0;

    const float4* __restrict__ VW4 = g_VW;

    // Prime pipeline with step 0's operands (both halves start reading at 0).
    float4 vw  = VW4[t];
    float4 x03, x47;
    {
        const float4* xs4 = reinterpret_cast<const float4*>(&sx8[0]);
        x03 = xs4[0];
        x47 = xs4[1];
    }

    if (half == 1) {
        // Accumulate-only replay of steps [0, 392): identical FMA sequence,
        // so the accumulator entering step 392 is bitwise equal to half 0's.
        #pragma unroll 2
        for (int i = 0; i < DHALF; i++) {
            const int ip = i + 1;
            float4 vw_n = VW4[ip * (H / 2) + t];
            const float4* xs4n = reinterpret_cast<const float4*>(&sx8[ip * 8]);
            float4 x03_n = xs4n[0];
            float4 x47_n = xs4n[1];

            A[0].x = fmaf(vw.z, x03.x, A[0].x);
            A[0].y = fmaf(vw.w, x03.x, A[0].y);
            A[1].x = fmaf(vw.z, x03.y, A[1].x);
            A[1].y = fmaf(vw.w, x03.y, A[1].y);
            A[2].x = fmaf(vw.z, x03.z, A[2].x);
            A[2].y = fmaf(vw.w, x03.z, A[2].y);
            A[3].x = fmaf(vw.z, x03.w, A[3].x);
            A[3].y = fmaf(vw.w, x03.w, A[3].y);
            A[4].x = fmaf(vw.z, x47.x, A[4].x);
            A[4].y = fmaf(vw.w, x47.x, A[4].y);
            A[5].x = fmaf(vw.z, x47.y, A[5].x);
            A[5].y = fmaf(vw.w, x47.y, A[5].y);
            A[6].x = fmaf(vw.z, x47.z, A[6].x);
            A[6].y = fmaf(vw.w, x47.z, A[6].y);

            vw = vw_n; x03 = x03_n; x47 = x47_n;
        }
        // Pipeline now holds step 392's operands.
    }

    const int istart = half * DHALF;

    for (int ch = 0; ch < NCHUNKS; ch++) {
        const int ibase = istart + ch * CHUNK;

        #pragma unroll 2
        for (int il = 0; il < CHUNK; il++) {
            const int i = ibase + il;
            // ---- prefetch next step's operands (fully overlapped) ----
            const int ip = (i + 1 < D) ? (i + 1) : (D - 1);
            float4 vw_n = VW4[ip * (H / 2) + t];
            const float4* xs4n = reinterpret_cast<const float4*>(&sx8[ip * 8]);
            float4 x03_n = xs4n[0];
            float4 x47_n = xs4n[1];

            // ---- compute current step ----
            float p0, p1, p2, p3, p4, p5, p6;
            {
                float t0, t1;
                tanh2(A[0].x, A[0].y, t0, t1); p0 = fmaf(vw.y, t1, vw.x * t0);
                tanh2(A[1].x, A[1].y, t0, t1); p1 = fmaf(vw.y, t1, vw.x * t0);
                tanh2(A[2].x, A[2].y, t0, t1); p2 = fmaf(vw.y, t1, vw.x * t0);
                tanh2(A[3].x, A[3].y, t0, t1); p3 = fmaf(vw.y, t1, vw.x * t0);
                tanh2(A[4].x, A[4].y, t0, t1); p4 = fmaf(vw.y, t1, vw.x * t0);
                tanh2(A[5].x, A[5].y, t0, t1); p5 = fmaf(vw.y, t1, vw.x * t0);
                tanh2(A[6].x, A[6].y, t0, t1); p6 = fmaf(vw.y, t1, vw.x * t0);
            }

            A[0].x = fmaf(vw.z, x03.x, A[0].x);
            A[0].y = fmaf(vw.w, x03.x, A[0].y);
            A[1].x = fmaf(vw.z, x03.y, A[1].x);
            A[1].y = fmaf(vw.w, x03.y, A[1].y);
            A[2].x = fmaf(vw.z, x03.z, A[2].x);
            A[2].y = fmaf(vw.w, x03.z, A[2].y);
            A[3].x = fmaf(vw.z, x03.w, A[3].x);
            A[3].y = fmaf(vw.w, x03.w, A[3].y);
            A[4].x = fmaf(vw.z, x47.x, A[4].x);
            A[4].y = fmaf(vw.w, x47.x, A[4].y);
            A[5].x = fmaf(vw.z, x47.y, A[5].x);
            A[5].y = fmaf(vw.w, x47.y, A[5].y);
            A[6].x = fmaf(vw.z, x47.z, A[6].x);
            A[6].y = fmaf(vw.w, x47.z, A[6].y);

            // Round-6 butterfly: both shuffles issued before the select.
            float e, f;
            e = __shfl_xor_sync(0xffffffffu, p0, 16);
            f = __shfl_xor_sync(0xffffffffu, p1, 16);
            float q01 = lo16 ? (p0 + e) : (p1 + f);
            e = __shfl_xor_sync(0xffffffffu, p2, 16);
            f = __shfl_xor_sync(0xffffffffu, p3, 16);
            float q23 = lo16 ? (p2 + e) : (p3 + f);
            e = __shfl_xor_sync(0xffffffffu, p4, 16);
            f = __shfl_xor_sync(0xffffffffu, p5, 16);
            float q45 = lo16 ? (p4 + e) : (p5 + f);
            e = __shfl_xor_sync(0xffffffffu, p6, 16);
            float q67 = lo16 ? (p6 + e) : 0.0f;   // slot 7 is zero

            e = __shfl_xor_sync(0xffffffffu, q01, 8);
            f = __shfl_xor_sync(0xffffffffu, q23, 8);
            float q0123 = lo8 ? (q01 + e) : (q23 + f);
            e = __shfl_xor_sync(0xffffffffu, q45, 8);
            f = __shfl_xor_sync(0xffffffffu, q67, 8);
            float q4567 = lo8 ? (q45 + e) : (q67 + f);

            e = __shfl_xor_sync(0xffffffffu, q0123, 4);
            f = __shfl_xor_sync(0xffffffffu, q4567, 4);
            float qq = lo4 ? (q0123 + e) : (q4567 + f);

            qq += __shfl_xor_sync(0xffffffffu, qq, 2);
            qq += __shfl_xor_sync(0xffffffffu, qq, 1);

            if (is_head) sp[(il * 16 + wid) * 8 + rowmap] = qq;

            // ---- rotate pipeline ----
            vw = vw_n; x03 = x03_n; x47 = x47_n;
        }

        __syncthreads();

        // Epilogue: for each (step, row) sum the 16 warp partials.
        for (int o = t; o < CHUNK * R; o += THREADS) {
            int il = o / R, r = o % R;
            float s = 0.0f;
            #pragma unroll
            for (int wi = 0; wi < 16; wi++)
                s += sp[(il * 16 + wi) * 8 + r];
            int i = ibase + il;
            int b = b0 + r;
            if (b < BATCH) out[b * D + i] = fmaf(0.5f, s, g_bias[i]);
        }

        __syncthreads();
    }
}

// ---------------------------------------------------------------------------
extern "C" void kernel_launch(void* const* d_in, const int* in_sizes, int n_in,
                              void* d_out, int out_size) {
    const float* pixels = (const float*)d_in[0];   // [1024, 784]
    const float* W      = (const float*)d_in[1];   // [1024, 784]
    const float* c      = (const float*)d_in[2];   // [1024]
    const float* V      = (const float*)d_in[3];   // [784, 1024]
    const float* bvec   = (const float*)d_in[4];   // [784]
    float* out          = (float*)d_out;           // [1024, 784]

    cudaFuncSetAttribute(nade_main, cudaFuncAttributeMaxDynamicSharedMemorySize,
                         SMEM_BYTES);
    cudaFuncSetAttribute(nade_main, cudaFuncAttributePreferredSharedMemoryCarveout,
                         100);

    prep_kernel<<<dim3(25, 33), dim3(32, 8)>>>(W, V, bvec);
    nade_main<<<NCTAS, THREADS, SMEM_BYTES>>>(pixels, c, out);
}

// round 13
// speedup vs baseline: 1.1082x; 1.1082x over previous
#include <cuda_runtime.h>
#include <cuda_bf16.h>
#include <cstdint>

#define D 784
#define H 1024
#define BATCH 1024
#define THREADS 512
#define R 7                      // batch rows per CTA
#define NCTAS 147                // 147*7 = 1029 >= 1024
#define CHUNK 56                 // 784 = 14 * 56; 56 = 4*14 -> clean unroll 4
#define NCHUNKS (D / CHUNK)
#define DPAD (D + 2)                         // padding rows for clamp-free prefetch
#define SX_BYTES (DPAD * 8 * 4)              // sx8[DPAD][8] = 25152
#define SP_BYTES (CHUNK * 16 * 8 * 4)        // sp[CHUNK][16][8] = 28672
#define SMEM_BYTES (SX_BYTES + SP_BYTES)     // 53824

// Scratch (no allocations allowed). +2 rows padding so prefetch of step i+1
// at i = D-1 stays in bounds without a clamp.
// g_VW[i*512 + t] = (V[i,2t], V[i,2t+1], W[2t,i], W[2t+1,i])
__device__ float4 g_VW[DPAD * (H / 2)];
__device__ float  g_bias[D];          // bias[i] = b[i] + 0.5 * sum_h V[i,h]

// Two tanh evaluations in ONE MUFU op via f16x2.
__device__ __forceinline__ void tanh2(float a, float b, float& ta, float& tb) {
    uint32_t pk, tk;
    asm("cvt.rn.f16x2.f32 %0, %1, %2;" : "=r"(pk) : "f"(b), "f"(a)); // lo=a, hi=b
    asm("tanh.approx.f16x2 %0, %1;" : "=r"(tk) : "r"(pk));
    asm("{\n\t.reg .b16 l, h;\n\t"
        "mov.b32 {l, h}, %2;\n\t"
        "cvt.f32.f16 %0, l;\n\t"
        "cvt.f32.f16 %1, h;\n\t}"
        : "=f"(ta), "=f"(tb) : "r"(tk));
}

// ---------------------------------------------------------------------------
// Fused prep: blockIdx.y < 32 -> build interleaved g_VW tile (transpose W via
//                                smem tile, merge with V)
//             blockIdx.y == 32 -> bias + zero-fill the two padding rows
// ---------------------------------------------------------------------------
__global__ void prep_kernel(const float* __restrict__ W,
                            const float* __restrict__ V,
                            const float* __restrict__ bvec) {
    if (blockIdx.y < 32) {
        __shared__ float tile[32][33];
        const int i0 = blockIdx.x * 32;
        const int h0 = blockIdx.y * 32;
        const int tx = threadIdx.x, ty = threadIdx.y;
        #pragma unroll
        for (int j = 0; j < 32; j += 8) {
            int ii = i0 + tx;
            if (ii < D) tile[ty + j][tx] = W[(h0 + ty + j) * D + ii];
        }
        __syncthreads();
        #pragma unroll
        for (int j = 0; j < 32; j += 8) {
            int i = i0 + ty + j;
            if (i < D && tx < 16) {
                int tcol = h0 / 2 + tx;
                float2 v2 = reinterpret_cast<const float2*>(V)[i * (H / 2) + tcol];
                g_VW[i * (H / 2) + tcol] =
                    make_float4(v2.x, v2.y, tile[2 * tx][i - i0], tile[2 * tx + 1][i - i0]);
            }
        }
    } else {
        int lane = threadIdx.x;
        int w    = threadIdx.y;
        #pragma unroll
        for (int k = 0; k < 4; k++) {
            int i = blockIdx.x * 32 + w * 4 + k;
            if (i >= D) continue;
            float s = 0.0f;
            #pragma unroll
            for (int j = 0; j < H / 32; j++) s += V[i * H + j * 32 + lane];
            #pragma unroll
            for (int o = 16; o > 0; o >>= 1)
                s += __shfl_xor_sync(0xffffffffu, s, o);
            if (lane == 0) g_bias[i] = bvec[i] + 0.5f * s;
        }
        // Zero the two padding rows of g_VW (read by the tail prefetch).
        if (blockIdx.x == 0) {
            int t = threadIdx.y * 32 + threadIdx.x;
            for (int k = t; k < 2 * (H / 2); k += 256)
                g_VW[D * (H / 2) + k] = make_float4(0.f, 0.f, 0.f, 0.f);
        }
    }
}

// ---------------------------------------------------------------------------
// Main: one CTA per 7 batch rows; 512 threads (16 warps), 2 h per lane.
// Software-pipelined distance-1 prefetch (clamp-free via padded arrays) +
// unroll 4 for a wide scheduling window. Round-6 butterfly reduction.
// ---------------------------------------------------------------------------
__global__ void __launch_bounds__(THREADS, 1)
nade_main(const float* __restrict__ pixels,
          const float* __restrict__ c,
          float* __restrict__ out) {
    extern __shared__ char smem_raw[];
    float* sx8 = reinterpret_cast<float*>(smem_raw);              // [DPAD][8]
    float* sp  = reinterpret_cast<float*>(smem_raw + SX_BYTES);   // [CHUNK][16][8]

    const int b0   = blockIdx.x * R;
    const int t    = threadIdx.x;
    const int lane = t & 31;
    const int wid  = t >> 5;

    for (int i = t; i < D; i += THREADS) {
        #pragma unroll
        for (int r = 0; r < R; r++) {
            int br = min(b0 + r, BATCH - 1);
            sx8[i * 8 + r] = 0.5f * pixels[br * D + i];
        }
        sx8[i * 8 + 7] = 0.0f;
    }
    // Zero the padding rows (avoid NaN-poisoned garbage in the tail prefetch).
    for (int k = t; k < 2 * 8; k += THREADS) sx8[D * 8 + k] = 0.0f;

    float2 A[R];
    {
        float2 cc = reinterpret_cast<const float2*>(c)[t];
        cc.x *= 0.5f; cc.y *= 0.5f;
        #pragma unroll
        for (int r = 0; r < R; r++) A[r] = cc;
    }
    __syncthreads();

    const bool lo16 = (lane & 16) == 0;
    const bool lo8  = (lane & 8)  == 0;
    const bool lo4  = (lane & 4)  == 0;
    const int rowmap = ((lane >> 4) & 1) | (((lane >> 3) & 1) << 1)
                     | (((lane >> 2) & 1) << 2);
    const bool is_head = (lane & 3) == 0;

    const float4* __restrict__ VW4 = g_VW;

    // Prime the pipeline with step 0's operands.
    float4 vw  = VW4[t];
    float4 x03, x47;
    {
        const float4* xs4 = reinterpret_cast<const float4*>(&sx8[0]);
        x03 = xs4[0];
        x47 = xs4[1];
    }

    for (int ch = 0; ch < NCHUNKS; ch++) {
        const int ibase = ch * CHUNK;

        #pragma unroll 4
        for (int il = 0; il < CHUNK; il++) {
            const int i = ibase + il;
            // ---- prefetch next step's operands (clamp-free, padded) ----
            float4 vw_n = VW4[(i + 1) * (H / 2) + t];
            const float4* xs4n = reinterpret_cast<const float4*>(&sx8[(i + 1) * 8]);
            float4 x03_n = xs4n[0];
            float4 x47_n = xs4n[1];

            // ---- compute current step ----
            float p0, p1, p2, p3, p4, p5, p6;
            {
                float t0, t1;
                tanh2(A[0].x, A[0].y, t0, t1); p0 = fmaf(vw.y, t1, vw.x * t0);
                tanh2(A[1].x, A[1].y, t0, t1); p1 = fmaf(vw.y, t1, vw.x * t0);
                tanh2(A[2].x, A[2].y, t0, t1); p2 = fmaf(vw.y, t1, vw.x * t0);
                tanh2(A[3].x, A[3].y, t0, t1); p3 = fmaf(vw.y, t1, vw.x * t0);
                tanh2(A[4].x, A[4].y, t0, t1); p4 = fmaf(vw.y, t1, vw.x * t0);
                tanh2(A[5].x, A[5].y, t0, t1); p5 = fmaf(vw.y, t1, vw.x * t0);
                tanh2(A[6].x, A[6].y, t0, t1); p6 = fmaf(vw.y, t1, vw.x * t0);
            }

            A[0].x = fmaf(vw.z, x03.x, A[0].x);
            A[0].y = fmaf(vw.w, x03.x, A[0].y);
            A[1].x = fmaf(vw.z, x03.y, A[1].x);
            A[1].y = fmaf(vw.w, x03.y, A[1].y);
            A[2].x = fmaf(vw.z, x03.z, A[2].x);
            A[2].y = fmaf(vw.w, x03.z, A[2].y);
            A[3].x = fmaf(vw.z, x03.w, A[3].x);
            A[3].y = fmaf(vw.w, x03.w, A[3].y);
            A[4].x = fmaf(vw.z, x47.x, A[4].x);
            A[4].y = fmaf(vw.w, x47.x, A[4].y);
            A[5].x = fmaf(vw.z, x47.y, A[5].x);
            A[5].y = fmaf(vw.w, x47.y, A[5].y);
            A[6].x = fmaf(vw.z, x47.z, A[6].x);
            A[6].y = fmaf(vw.w, x47.z, A[6].y);

            // Round-6 butterfly: both shuffles issued before the select.
            float e, f;
            e = __shfl_xor_sync(0xffffffffu, p0, 16);
            f = __shfl_xor_sync(0xffffffffu, p1, 16);
            float q01 = lo16 ? (p0 + e) : (p1 + f);
            e = __shfl_xor_sync(0xffffffffu, p2, 16);
            f = __shfl_xor_sync(0xffffffffu, p3, 16);
            float q23 = lo16 ? (p2 + e) : (p3 + f);
            e = __shfl_xor_sync(0xffffffffu, p4, 16);
            f = __shfl_xor_sync(0xffffffffu, p5, 16);
            float q45 = lo16 ? (p4 + e) : (p5 + f);
            e = __shfl_xor_sync(0xffffffffu, p6, 16);
            float q67 = lo16 ? (p6 + e) : 0.0f;   // slot 7 is zero

            e = __shfl_xor_sync(0xffffffffu, q01, 8);
            f = __shfl_xor_sync(0xffffffffu, q23, 8);
            float q0123 = lo8 ? (q01 + e) : (q23 + f);
            e = __shfl_xor_sync(0xffffffffu, q45, 8);
            f = __shfl_xor_sync(0xffffffffu, q67, 8);
            float q4567 = lo8 ? (q45 + e) : (q67 + f);

            e = __shfl_xor_sync(0xffffffffu, q0123, 4);
            f = __shfl_xor_sync(0xffffffffu, q4567, 4);
            float qq = lo4 ? (q0123 + e) : (q4567 + f);

            qq += __shfl_xor_sync(0xffffffffu, qq, 2);
            qq += __shfl_xor_sync(0xffffffffu, qq, 1);

            if (is_head) sp[(il * 16 + wid) * 8 + rowmap] = qq;

            // ---- rotate pipeline ----
            vw = vw_n; x03 = x03_n; x47 = x47_n;
        }

        __syncthreads();

        // Epilogue: for each (step, row) sum the 16 warp partials.
        for (int o = t; o < CHUNK * R; o += THREADS) {
            int il = o / R, r = o % R;
            float s = 0.0f;
            #pragma unroll
            for (int wi = 0; wi < 16; wi++)
                s += sp[(il * 16 + wi) * 8 + r];
            int i = ibase + il;
            int b = b0 + r;
            if (b < BATCH) out[b * D + i] = fmaf(0.5f, s, g_bias[i]);
        }

        __syncthreads();
    }
}

// ---------------------------------------------------------------------------
extern "C" void kernel_launch(void* const* d_in, const int* in_sizes, int n_in,
                              void* d_out, int out_size) {
    const float* pixels = (const float*)d_in[0];   // [1024, 784]
    const float* W      = (const float*)d_in[1];   // [1024, 784]
    const float* c      = (const float*)d_in[2];   // [1024]
    const float* V      = (const float*)d_in[3];   // [784, 1024]
    const float* bvec   = (const float*)d_in[4];   // [784]
    float* out          = (float*)d_out;           // [1024, 784]

    cudaFuncSetAttribute(nade_main, cudaFuncAttributeMaxDynamicSharedMemorySize,
                         SMEM_BYTES);
    cudaFuncSetAttribute(nade_main, cudaFuncAttributePreferredSharedMemoryCarveout,
                         100);

    prep_kernel<<<dim3(25, 33), dim3(32, 8)>>>(W, V, bvec);
    nade_main<<<NCTAS, THREADS, SMEM_BYTES>>>(pixels, c, out);
}

// round 14
// speedup vs baseline: 1.2491x; 1.1272x over previous
#include <cuda_runtime.h>
#include <cuda_bf16.h>
#include <cstdint>

#define D 784
#define H 1024
#define BATCH 1024
#define THREADS 512
#define R 7                      // batch rows per CTA
#define NCTAS 147                // 147*7 = 1029 >= 1024
#define CHUNK 98                 // 784 = 8 * 98 (even trip count, unroll-2 friendly)
#define NCHUNKS (D / CHUNK)
#define DPAD (D + 2)                         // padding rows for clamp-free prefetch
#define SX_BYTES (DPAD * 8 * 4)              // sx8[DPAD][8] = 25152
#define SP_BYTES (CHUNK * 16 * 8 * 4)        // sp[CHUNK][16][8] = 50176
#define SMEM_BYTES (SX_BYTES + SP_BYTES)     // 75328

// Scratch (no allocations allowed). +2 rows padding so the prefetch of step
// i+1 at i = D-1 stays in bounds without a clamp.
// g_VW[i*512 + t] = (V[i,2t], V[i,2t+1], W[2t,i], W[2t+1,i])
__device__ float4 g_VW[DPAD * (H / 2)];
__device__ float  g_bias[D];          // bias[i] = b[i] + 0.5 * sum_h V[i,h]

// Two tanh evaluations in ONE MUFU op via f16x2.
__device__ __forceinline__ void tanh2(float a, float b, float& ta, float& tb) {
    uint32_t pk, tk;
    asm("cvt.rn.f16x2.f32 %0, %1, %2;" : "=r"(pk) : "f"(b), "f"(a)); // lo=a, hi=b
    asm("tanh.approx.f16x2 %0, %1;" : "=r"(tk) : "r"(pk));
    asm("{\n\t.reg .b16 l, h;\n\t"
        "mov.b32 {l, h}, %2;\n\t"
        "cvt.f32.f16 %0, l;\n\t"
        "cvt.f32.f16 %1, h;\n\t}"
        : "=f"(ta), "=f"(tb) : "r"(tk));
}

// ---------------------------------------------------------------------------
// Fused prep: blockIdx.y < 32 -> build interleaved g_VW tile (transpose W via
//                                smem tile, merge with V)
//             blockIdx.y == 32 -> bias + zero-fill g_VW padding rows
// ---------------------------------------------------------------------------
__global__ void prep_kernel(const float* __restrict__ W,
                            const float* __restrict__ V,
                            const float* __restrict__ bvec) {
    if (blockIdx.y < 32) {
        __shared__ float tile[32][33];
        const int i0 = blockIdx.x * 32;
        const int h0 = blockIdx.y * 32;
        const int tx = threadIdx.x, ty = threadIdx.y;
        #pragma unroll
        for (int j = 0; j < 32; j += 8) {
            int ii = i0 + tx;
            if (ii < D) tile[ty + j][tx] = W[(h0 + ty + j) * D + ii];
        }
        __syncthreads();
        #pragma unroll
        for (int j = 0; j < 32; j += 8) {
            int i = i0 + ty + j;
            if (i < D && tx < 16) {
                int tcol = h0 / 2 + tx;
                float2 v2 = reinterpret_cast<const float2*>(V)[i * (H / 2) + tcol];
                g_VW[i * (H / 2) + tcol] =
                    make_float4(v2.x, v2.y, tile[2 * tx][i - i0], tile[2 * tx + 1][i - i0]);
            }
        }
    } else {
        int lane = threadIdx.x;
        int w    = threadIdx.y;
        #pragma unroll
        for (int k = 0; k < 4; k++) {
            int i = blockIdx.x * 32 + w * 4 + k;
            if (i >= D) continue;
            float s = 0.0f;
            #pragma unroll
            for (int j = 0; j < H / 32; j++) s += V[i * H + j * 32 + lane];
            #pragma unroll
            for (int o = 16; o > 0; o >>= 1)
                s += __shfl_xor_sync(0xffffffffu, s, o);
            if (lane == 0) g_bias[i] = bvec[i] + 0.5f * s;
        }
        // Zero the two padding rows of g_VW (read by the tail prefetch).
        if (blockIdx.x == 0) {
            int t = threadIdx.y * 32 + threadIdx.x;
            for (int k = t; k < 2 * (H / 2); k += 256)
                g_VW[D * (H / 2) + k] = make_float4(0.f, 0.f, 0.f, 0.f);
        }
    }
}

// ---------------------------------------------------------------------------
// Main: one CTA per 7 batch rows; 512 threads (16 warps), 2 h per lane.
// Round-10 schedule: software-pipelined distance-1 prefetch, unroll 2,
// butterfly reduction, deferred chunk epilogue. The only change vs the
// 226.5us kernel: clamp-free prefetch addressing via padded arrays.
// ---------------------------------------------------------------------------
__global__ void __launch_bounds__(THREADS, 1)
nade_main(const float* __restrict__ pixels,
          const float* __restrict__ c,
          float* __restrict__ out) {
    extern __shared__ char smem_raw[];
    float* sx8 = reinterpret_cast<float*>(smem_raw);              // [DPAD][8]
    float* sp  = reinterpret_cast<float*>(smem_raw + SX_BYTES);   // [CHUNK][16][8]

    const int b0   = blockIdx.x * R;
    const int t    = threadIdx.x;
    const int lane = t & 31;
    const int wid  = t >> 5;

    for (int i = t; i < D; i += THREADS) {
        #pragma unroll
        for (int r = 0; r < R; r++) {
            int br = min(b0 + r, BATCH - 1);
            sx8[i * 8 + r] = 0.5f * pixels[br * D + i];
        }
        sx8[i * 8 + 7] = 0.0f;
    }
    // Zero the padding rows (keep tail prefetch values benign).
    for (int k = t; k < 2 * 8; k += THREADS) sx8[D * 8 + k] = 0.0f;

    float2 A[R];
    {
        float2 cc = reinterpret_cast<const float2*>(c)[t];
        cc.x *= 0.5f; cc.y *= 0.5f;
        #pragma unroll
        for (int r = 0; r < R; r++) A[r] = cc;
    }
    __syncthreads();

    const bool lo16 = (lane & 16) == 0;
    const bool lo8  = (lane & 8)  == 0;
    const bool lo4  = (lane & 4)  == 0;
    const int rowmap = ((lane >> 4) & 1) | (((lane >> 3) & 1) << 1)
                     | (((lane >> 2) & 1) << 2);
    const bool is_head = (lane & 3) == 0;

    const float4* __restrict__ VW4 = g_VW;

    // Prime the pipeline with step 0's operands.
    float4 vw  = VW4[t];
    float4 x03, x47;
    {
        const float4* xs4 = reinterpret_cast<const float4*>(&sx8[0]);
        x03 = xs4[0];
        x47 = xs4[1];
    }

    for (int ch = 0; ch < NCHUNKS; ch++) {
        const int ibase = ch * CHUNK;

        #pragma unroll 2
        for (int il = 0; il < CHUNK; il++) {
            const int i = ibase + il;
            // ---- prefetch next step's operands (clamp-free, padded) ----
            float4 vw_n = VW4[(i + 1) * (H / 2) + t];
            const float4* xs4n = reinterpret_cast<const float4*>(&sx8[(i + 1) * 8]);
            float4 x03_n = xs4n[0];
            float4 x47_n = xs4n[1];

            // ---- compute current step ----
            float p0, p1, p2, p3, p4, p5, p6;
            {
                float t0, t1;
                tanh2(A[0].x, A[0].y, t0, t1); p0 = fmaf(vw.y, t1, vw.x * t0);
                tanh2(A[1].x, A[1].y, t0, t1); p1 = fmaf(vw.y, t1, vw.x * t0);
                tanh2(A[2].x, A[2].y, t0, t1); p2 = fmaf(vw.y, t1, vw.x * t0);
                tanh2(A[3].x, A[3].y, t0, t1); p3 = fmaf(vw.y, t1, vw.x * t0);
                tanh2(A[4].x, A[4].y, t0, t1); p4 = fmaf(vw.y, t1, vw.x * t0);
                tanh2(A[5].x, A[5].y, t0, t1); p5 = fmaf(vw.y, t1, vw.x * t0);
                tanh2(A[6].x, A[6].y, t0, t1); p6 = fmaf(vw.y, t1, vw.x * t0);
            }

            A[0].x = fmaf(vw.z, x03.x, A[0].x);
            A[0].y = fmaf(vw.w, x03.x, A[0].y);
            A[1].x = fmaf(vw.z, x03.y, A[1].x);
            A[1].y = fmaf(vw.w, x03.y, A[1].y);
            A[2].x = fmaf(vw.z, x03.z, A[2].x);
            A[2].y = fmaf(vw.w, x03.z, A[2].y);
            A[3].x = fmaf(vw.z, x03.w, A[3].x);
            A[3].y = fmaf(vw.w, x03.w, A[3].y);
            A[4].x = fmaf(vw.z, x47.x, A[4].x);
            A[4].y = fmaf(vw.w, x47.x, A[4].y);
            A[5].x = fmaf(vw.z, x47.y, A[5].x);
            A[5].y = fmaf(vw.w, x47.y, A[5].y);
            A[6].x = fmaf(vw.z, x47.z, A[6].x);
            A[6].y = fmaf(vw.w, x47.z, A[6].y);

            // Round-6 butterfly: both shuffles issued before the select.
            float e, f;
            e = __shfl_xor_sync(0xffffffffu, p0, 16);
            f = __shfl_xor_sync(0xffffffffu, p1, 16);
            float q01 = lo16 ? (p0 + e) : (p1 + f);
            e = __shfl_xor_sync(0xffffffffu, p2, 16);
            f = __shfl_xor_sync(0xffffffffu, p3, 16);
            float q23 = lo16 ? (p2 + e) : (p3 + f);
            e = __shfl_xor_sync(0xffffffffu, p4, 16);
            f = __shfl_xor_sync(0xffffffffu, p5, 16);
            float q45 = lo16 ? (p4 + e) : (p5 + f);
            e = __shfl_xor_sync(0xffffffffu, p6, 16);
            float q67 = lo16 ? (p6 + e) : 0.0f;   // slot 7 is zero

            e = __shfl_xor_sync(0xffffffffu, q01, 8);
            f = __shfl_xor_sync(0xffffffffu, q23, 8);
            float q0123 = lo8 ? (q01 + e) : (q23 + f);
            e = __shfl_xor_sync(0xffffffffu, q45, 8);
            f = __shfl_xor_sync(0xffffffffu, q67, 8);
            float q4567 = lo8 ? (q45 + e) : (q67 + f);

            e = __shfl_xor_sync(0xffffffffu, q0123, 4);
            f = __shfl_xor_sync(0xffffffffu, q4567, 4);
            float qq = lo4 ? (q0123 + e) : (q4567 + f);

            qq += __shfl_xor_sync(0xffffffffu, qq, 2);
            qq += __shfl_xor_sync(0xffffffffu, qq, 1);

            if (is_head) sp[(il * 16 + wid) * 8 + rowmap] = qq;

            // ---- rotate pipeline ----
            vw = vw_n; x03 = x03_n; x47 = x47_n;
        }

        __syncthreads();

        // Epilogue: for each (step, row) sum the 16 warp partials.
        for (int o = t; o < CHUNK * R; o += THREADS) {
            int il = o / R, r = o % R;
            float s = 0.0f;
            #pragma unroll
            for (int wi = 0; wi < 16; wi++)
                s += sp[(il * 16 + wi) * 8 + r];
            int i = ibase + il;
            int b = b0 + r;
            if (b < BATCH) out[b * D + i] = fmaf(0.5f, s, g_bias[i]);
        }

        __syncthreads();
    }
}

// ---------------------------------------------------------------------------
extern "C" void kernel_launch(void* const* d_in, const int* in_sizes, int n_in,
                              void* d_out, int out_size) {
    const float* pixels = (const float*)d_in[0];   // [1024, 784]
    const float* W      = (const float*)d_in[1];   // [1024, 784]
    const float* c      = (const float*)d_in[2];   // [1024]
    const float* V      = (const float*)d_in[3];   // [784, 1024]
    const float* bvec   = (const float*)d_in[4];   // [784]
    float* out          = (float*)d_out;           // [1024, 784]

    cudaFuncSetAttribute(nade_main, cudaFuncAttributeMaxDynamicSharedMemorySize,
                         SMEM_BYTES);
    cudaFuncSetAttribute(nade_main, cudaFuncAttributePreferredSharedMemoryCarveout,
                         100);

    prep_kernel<<<dim3(25, 33), dim3(32, 8)>>>(W, V, bvec);
    nade_main<<<NCTAS, THREADS, SMEM_BYTES>>>(pixels, c, out);
}

// round 15
// speedup vs baseline: 1.2728x; 1.0190x over previous
#include <cuda_runtime.h>
#include <cuda_bf16.h>
#include <cstdint>

#define D 784
#define H 1024
#define BATCH 1024
#define THREADS 512
#define R 7                      // batch rows per CTA
#define NCTAS 147                // 147*7 = 1029 >= 1024
#define CHUNK 98                 // 784 = 8 * 98 (even trip count, unroll-2 friendly)
#define NCHUNKS (D / CHUNK)
#define DPAD (D + 2)                         // padding rows for clamp-free prefetch
#define SX_BYTES (DPAD * 8 * 4)              // sx8[DPAD][8] = 25152
#define SP_BYTES (CHUNK * 16 * 32 * 4)       // sp[CHUNK][16][32] = 200704
#define SMEM_BYTES (SX_BYTES + SP_BYTES)     // 225856 (<= 227KB/CTA limit)

// Scratch (no allocations allowed). +2 rows padding so the prefetch of step
// i+1 at i = D-1 stays in bounds without a clamp.
// g_VW[i*512 + t] = (V[i,2t], V[i,2t+1], W[2t,i], W[2t+1,i])
__device__ float4 g_VW[DPAD * (H / 2)];
__device__ float  g_bias[D];          // bias[i] = b[i] + 0.5 * sum_h V[i,h]

// Two tanh evaluations in ONE MUFU op via f16x2.
__device__ __forceinline__ void tanh2(float a, float b, float& ta, float& tb) {
    uint32_t pk, tk;
    asm("cvt.rn.f16x2.f32 %0, %1, %2;" : "=r"(pk) : "f"(b), "f"(a)); // lo=a, hi=b
    asm("tanh.approx.f16x2 %0, %1;" : "=r"(tk) : "r"(pk));
    asm("{\n\t.reg .b16 l, h;\n\t"
        "mov.b32 {l, h}, %2;\n\t"
        "cvt.f32.f16 %0, l;\n\t"
        "cvt.f32.f16 %1, h;\n\t}"
        : "=f"(ta), "=f"(tb) : "r"(tk));
}

// ---------------------------------------------------------------------------
// Fused prep: blockIdx.y < 32 -> build interleaved g_VW tile (transpose W via
//                                smem tile, merge with V)
//             blockIdx.y == 32 -> bias + zero-fill g_VW padding rows
// ---------------------------------------------------------------------------
__global__ void prep_kernel(const float* __restrict__ W,
                            const float* __restrict__ V,
                            const float* __restrict__ bvec) {
    if (blockIdx.y < 32) {
        __shared__ float tile[32][33];
        const int i0 = blockIdx.x * 32;
        const int h0 = blockIdx.y * 32;
        const int tx = threadIdx.x, ty = threadIdx.y;
        #pragma unroll
        for (int j = 0; j < 32; j += 8) {
            int ii = i0 + tx;
            if (ii < D) tile[ty + j][tx] = W[(h0 + ty + j) * D + ii];
        }
        __syncthreads();
        #pragma unroll
        for (int j = 0; j < 32; j += 8) {
            int i = i0 + ty + j;
            if (i < D && tx < 16) {
                int tcol = h0 / 2 + tx;
                float2 v2 = reinterpret_cast<const float2*>(V)[i * (H / 2) + tcol];
                g_VW[i * (H / 2) + tcol] =
                    make_float4(v2.x, v2.y, tile[2 * tx][i - i0], tile[2 * tx + 1][i - i0]);
            }
        }
    } else {
        int lane = threadIdx.x;
        int w    = threadIdx.y;
        #pragma unroll
        for (int k = 0; k < 4; k++) {
            int i = blockIdx.x * 32 + w * 4 + k;
            if (i >= D) continue;
            float s = 0.0f;
            #pragma unroll
            for (int j = 0; j < H / 32; j++) s += V[i * H + j * 32 + lane];
            #pragma unroll
            for (int o = 16; o > 0; o >>= 1)
                s += __shfl_xor_sync(0xffffffffu, s, o);
            if (lane == 0) g_bias[i] = bvec[i] + 0.5f * s;
        }
        // Zero the two padding rows of g_VW (read by the tail prefetch).
        if (blockIdx.x == 0) {
            int t = threadIdx.y * 32 + threadIdx.x;
            for (int k = t; k < 2 * (H / 2); k += 256)
                g_VW[D * (H / 2) + k] = make_float4(0.f, 0.f, 0.f, 0.f);
        }
    }
}

// ---------------------------------------------------------------------------
// Main: one CTA per 7 batch rows; 512 threads (16 warps), 2 h per lane.
// r14 schedule (software-pipelined distance-1 clamp-free prefetch, unroll 2)
// with the butterfly cut at 4-lane granularity: the last two shuffle levels
// move to the chunk epilogue. All 32 lanes store their 4-lane slot partial
// (one conflict-free 128B STS wavefront); epilogue sums 16 warps x 4 lanes.
// ---------------------------------------------------------------------------
__global__ void __launch_bounds__(THREADS, 1)
nade_main(const float* __restrict__ pixels,
          const float* __restrict__ c,
          float* __restrict__ out) {
    extern __shared__ char smem_raw[];
    float* sx8 = reinterpret_cast<float*>(smem_raw);              // [DPAD][8]
    float* sp  = reinterpret_cast<float*>(smem_raw + SX_BYTES);   // [CHUNK][16][32]

    const int b0   = blockIdx.x * R;
    const int t    = threadIdx.x;
    const int lane = t & 31;
    const int wid  = t >> 5;

    for (int i = t; i < D; i += THREADS) {
        #pragma unroll
        for (int r = 0; r < R; r++) {
            int br = min(b0 + r, BATCH - 1);
            sx8[i * 8 + r] = 0.5f * pixels[br * D + i];
        }
        sx8[i * 8 + 7] = 0.0f;
    }
    // Zero the padding rows (keep tail prefetch values benign).
    for (int k = t; k < 2 * 8; k += THREADS) sx8[D * 8 + k] = 0.0f;

    float2 A[R];
    {
        float2 cc = reinterpret_cast<const float2*>(c)[t];
        cc.x *= 0.5f; cc.y *= 0.5f;
        #pragma unroll
        for (int r = 0; r < R; r++) A[r] = cc;
    }
    __syncthreads();

    const bool lo16 = (lane & 16) == 0;
    const bool lo8  = (lane & 8)  == 0;
    const bool lo4  = (lane & 4)  == 0;
    // Slot held by this lane after the 3 fold levels.
    const int rowmap = ((lane >> 4) & 1) | (((lane >> 3) & 1) << 1)
                     | (((lane >> 2) & 1) << 2);
    // STS target: permutation of 32 consecutive floats -> conflict-free.
    const int sts_off = rowmap * 4 + (lane & 3);

    const float4* __restrict__ VW4 = g_VW;

    // Prime the pipeline with step 0's operands.
    float4 vw  = VW4[t];
    float4 x03, x47;
    {
        const float4* xs4 = reinterpret_cast<const float4*>(&sx8[0]);
        x03 = xs4[0];
        x47 = xs4[1];
    }

    for (int ch = 0; ch < NCHUNKS; ch++) {
        const int ibase = ch * CHUNK;

        #pragma unroll 2
        for (int il = 0; il < CHUNK; il++) {
            const int i = ibase + il;
            // ---- prefetch next step's operands (clamp-free, padded) ----
            float4 vw_n = VW4[(i + 1) * (H / 2) + t];
            const float4* xs4n = reinterpret_cast<const float4*>(&sx8[(i + 1) * 8]);
            float4 x03_n = xs4n[0];
            float4 x47_n = xs4n[1];

            // ---- compute current step ----
            float p0, p1, p2, p3, p4, p5, p6;
            {
                float t0, t1;
                tanh2(A[0].x, A[0].y, t0, t1); p0 = fmaf(vw.y, t1, vw.x * t0);
                tanh2(A[1].x, A[1].y, t0, t1); p1 = fmaf(vw.y, t1, vw.x * t0);
                tanh2(A[2].x, A[2].y, t0, t1); p2 = fmaf(vw.y, t1, vw.x * t0);
                tanh2(A[3].x, A[3].y, t0, t1); p3 = fmaf(vw.y, t1, vw.x * t0);
                tanh2(A[4].x, A[4].y, t0, t1); p4 = fmaf(vw.y, t1, vw.x * t0);
                tanh2(A[5].x, A[5].y, t0, t1); p5 = fmaf(vw.y, t1, vw.x * t0);
                tanh2(A[6].x, A[6].y, t0, t1); p6 = fmaf(vw.y, t1, vw.x * t0);
            }

            A[0].x = fmaf(vw.z, x03.x, A[0].x);
            A[0].y = fmaf(vw.w, x03.x, A[0].y);
            A[1].x = fmaf(vw.z, x03.y, A[1].x);
            A[1].y = fmaf(vw.w, x03.y, A[1].y);
            A[2].x = fmaf(vw.z, x03.z, A[2].x);
            A[2].y = fmaf(vw.w, x03.z, A[2].y);
            A[3].x = fmaf(vw.z, x03.w, A[3].x);
            A[3].y = fmaf(vw.w, x03.w, A[3].y);
            A[4].x = fmaf(vw.z, x47.x, A[4].x);
            A[4].y = fmaf(vw.w, x47.x, A[4].y);
            A[5].x = fmaf(vw.z, x47.y, A[5].x);
            A[5].y = fmaf(vw.w, x47.y, A[5].y);
            A[6].x = fmaf(vw.z, x47.z, A[6].x);
            A[6].y = fmaf(vw.w, x47.z, A[6].y);

            // Butterfly (r6 shape: shuffles before selects), cut after the
            // mask-4 level: every lane then holds a 4-lane partial of slot
            // 'rowmap'. The remaining x4 compression happens in the epilogue.
            float e, f;
            e = __shfl_xor_sync(0xffffffffu, p0, 16);
            f = __shfl_xor_sync(0xffffffffu, p1, 16);
            float q01 = lo16 ? (p0 + e) : (p1 + f);
            e = __shfl_xor_sync(0xffffffffu, p2, 16);
            f = __shfl_xor_sync(0xffffffffu, p3, 16);
            float q23 = lo16 ? (p2 + e) : (p3 + f);
            e = __shfl_xor_sync(0xffffffffu, p4, 16);
            f = __shfl_xor_sync(0xffffffffu, p5, 16);
            float q45 = lo16 ? (p4 + e) : (p5 + f);
            e = __shfl_xor_sync(0xffffffffu, p6, 16);
            float q67 = lo16 ? (p6 + e) : 0.0f;   // slot 7 is zero

            e = __shfl_xor_sync(0xffffffffu, q01, 8);
            f = __shfl_xor_sync(0xffffffffu, q23, 8);
            float q0123 = lo8 ? (q01 + e) : (q23 + f);
            e = __shfl_xor_sync(0xffffffffu, q45, 8);
            f = __shfl_xor_sync(0xffffffffu, q67, 8);
            float q4567 = lo8 ? (q45 + e) : (q67 + f);

            e = __shfl_xor_sync(0xffffffffu, q0123, 4);
            f = __shfl_xor_sync(0xffffffffu, q4567, 4);
            float qq = lo4 ? (q0123 + e) : (q4567 + f);

            // All 32 lanes store: one conflict-free 128B wavefront.
            sp[(il * 16 + wid) * 32 + sts_off] = qq;

            // ---- rotate pipeline ----
            vw = vw_n; x03 = x03_n; x47 = x47_n;
        }

        __syncthreads();

        // Epilogue: for each (step, row) sum 16 warps x 4 lane-partials.
        for (int o = t; o < CHUNK * R; o += THREADS) {
            int il = o / R, r = o % R;
            float s = 0.0f;
            #pragma unroll
            for (int wi = 0; wi < 16; wi++) {
                const float4 q = *reinterpret_cast<const float4*>(
                    &sp[(il * 16 + wi) * 32 + r * 4]);
                s += (q.x + q.y) + (q.z + q.w);
            }
            int i = ibase + il;
            int b = b0 + r;
            if (b < BATCH) out[b * D + i] = fmaf(0.5f, s, g_bias[i]);
        }

        __syncthreads();
    }
}

// ---------------------------------------------------------------------------
extern "C" void kernel_launch(void* const* d_in, const int* in_sizes, int n_in,
                              void* d_out, int out_size) {
    const float* pixels = (const float*)d_in[0];   // [1024, 784]
    const float* W      = (const float*)d_in[1];   // [1024, 784]
    const float* c      = (const float*)d_in[2];   // [1024]
    const float* V      = (const float*)d_in[3];   // [784, 1024]
    const float* bvec   = (const float*)d_in[4];   // [784]
    float* out          = (float*)d_out;           // [1024, 784]

    cudaFuncSetAttribute(nade_main, cudaFuncAttributeMaxDynamicSharedMemorySize,
                         SMEM_BYTES);
    cudaFuncSetAttribute(nade_main, cudaFuncAttributePreferredSharedMemoryCarveout,
                         100);

    prep_kernel<<<dim3(25, 33), dim3(32, 8)>>>(W, V, bvec);
    nade_main<<<NCTAS, THREADS, SMEM_BYTES>>>(pixels, c, out);
}